// round 1
// baseline (speedup 1.0000x reference)
#include <cuda_runtime.h>
#include <cstdint>

// Problem constants
#define NB   8
#define SLQ  2048
#define SLK  2048
#define DIM  128

// Smem row strides (pad +4 floats: keeps float4 alignment, spreads banks)
#define QSTR 132
#define PSTR 68

// Projection scratch (device globals: no allocation allowed in kernel_launch)
__device__ float g_q[NB * SLQ * DIM];
__device__ float g_k[NB * SLK * DIM];
__device__ float g_v[NB * SLK * DIM];

// ---------------------------------------------------------------------------
// Projection: Y[R,128] = X[R,128] @ W[128,128]
// 64-row tile per block, 256 threads, 4x8 register tile per thread.
// ---------------------------------------------------------------------------
__global__ __launch_bounds__(256, 1)
void proj_kernel(const float* __restrict__ X, const float* __restrict__ W,
                 float* __restrict__ Y) {
    extern __shared__ float sm[];
    float* sW = sm;                 // 128*128
    float* sX = sm + 128 * 128;     // 64*QSTR

    const int tid = threadIdx.x;
    const long r0 = (long)blockIdx.x * 64;

    // Load W (row-major, float4, conflict-free)
    for (int idx = tid; idx < 128 * 32; idx += 256) {
        int row = idx >> 5, k4 = (idx & 31) << 2;
        *(float4*)&sW[row * 128 + k4] = *(const float4*)&W[row * 128 + k4];
    }
    // Load X tile
    for (int idx = tid; idx < 64 * 32; idx += 256) {
        int row = idx >> 5, k4 = (idx & 31) << 2;
        *(float4*)&sX[row * QSTR + k4] = *(const float4*)&X[(r0 + row) * DIM + k4];
    }
    __syncthreads();

    const int tr = tid >> 4;   // 0..15 -> rows tr*4..tr*4+3
    const int tc = tid & 15;   // 0..15 -> cols tc+16*j, j=0..7

    float acc[4][8];
#pragma unroll
    for (int i = 0; i < 4; i++)
#pragma unroll
        for (int j = 0; j < 8; j++) acc[i][j] = 0.f;

#pragma unroll 4
    for (int k = 0; k < 128; k++) {
        float xv[4], wv[8];
#pragma unroll
        for (int i = 0; i < 4; i++) xv[i] = sX[(tr * 4 + i) * QSTR + k];
#pragma unroll
        for (int j = 0; j < 8; j++) wv[j] = sW[k * 128 + tc + 16 * j];
#pragma unroll
        for (int i = 0; i < 4; i++)
#pragma unroll
            for (int j = 0; j < 8; j++) acc[i][j] = fmaf(xv[i], wv[j], acc[i][j]);
    }

#pragma unroll
    for (int i = 0; i < 4; i++)
#pragma unroll
        for (int j = 0; j < 8; j++)
            Y[(r0 + tr * 4 + i) * DIM + tc + 16 * j] = acc[i][j];
}

// ---------------------------------------------------------------------------
// Flash attention (fp32). Block = 64 Q rows; loop over K/V in 64-row tiles.
// 256 threads: tid = tr*16+tc. S tile per thread: 4 rows x 4 cols (c=tc+16j).
// O tile per thread: 4 rows x 8 cols. Online softmax state per row, reduced
// across the 16-lane tc-group with shfl_xor.
// ---------------------------------------------------------------------------
__global__ __launch_bounds__(256, 1)
void attn_kernel(const int* __restrict__ mask, float* __restrict__ out) {
    extern __shared__ float sm[];
    float* sQ = sm;                  // 64*QSTR
    float* sK = sQ + 64 * QSTR;      // 64*QSTR
    float* sV = sK + 64 * QSTR;      // 64*QSTR
    float* sP = sV + 64 * QSTR;      // 64*PSTR

    const int tid = threadIdx.x;
    const int b   = blockIdx.x >> 5;         // SLQ/64 = 32 q-blocks per batch
    const int q0  = (blockIdx.x & 31) << 6;

    const float* __restrict__ Q  = g_q + ((long)b * SLQ + q0) * DIM;
    const float* __restrict__ K  = g_k + (long)b * SLK * DIM;
    const float* __restrict__ V  = g_v + (long)b * SLK * DIM;
    const int*   __restrict__ Mb = mask + (long)b * SLK;

    // Load Q tile once
    for (int idx = tid; idx < 64 * 32; idx += 256) {
        int row = idx >> 5, k4 = (idx & 31) << 2;
        *(float4*)&sQ[row * QSTR + k4] = *(const float4*)&Q[row * DIM + k4];
    }

    const int tr = tid >> 4;
    const int tc = tid & 15;

    float O[4][8];
    float mrow[4], lrow[4];
#pragma unroll
    for (int i = 0; i < 4; i++) {
        mrow[i] = -1e30f;
        lrow[i] = 0.f;
#pragma unroll
        for (int j = 0; j < 8; j++) O[i][j] = 0.f;
    }
    const float scale = 0.08838834764831845f;  // 1/sqrt(128)

    for (int kt = 0; kt < SLK / 64; kt++) {
        const int n0 = kt << 6;
        __syncthreads();  // prior PV reads of sK/sV/sP done (1st iter: Q visible)
        for (int idx = tid; idx < 64 * 32; idx += 256) {
            int row = idx >> 5, k4 = (idx & 31) << 2;
            *(float4*)&sK[row * QSTR + k4] = *(const float4*)&K[(n0 + row) * DIM + k4];
            *(float4*)&sV[row * QSTR + k4] = *(const float4*)&V[(n0 + row) * DIM + k4];
        }
        __syncthreads();

        // ---- S = Q @ K^T (4x4 per thread), outer loop over k ----
        float s[4][4];
#pragma unroll
        for (int i = 0; i < 4; i++)
#pragma unroll
            for (int j = 0; j < 4; j++) s[i][j] = 0.f;

#pragma unroll 4
        for (int k = 0; k < 128; k++) {
            float qv[4], kv[4];
#pragma unroll
            for (int i = 0; i < 4; i++) qv[i] = sQ[(tr * 4 + i) * QSTR + k];
#pragma unroll
            for (int j = 0; j < 4; j++) kv[j] = sK[(tc + 16 * j) * QSTR + k];
#pragma unroll
            for (int i = 0; i < 4; i++)
#pragma unroll
                for (int j = 0; j < 4; j++) s[i][j] = fmaf(qv[i], kv[j], s[i][j]);
        }

        // scale + additive mask (mask==0 -> -inf; dataset mask is all ones)
        int mm[4];
#pragma unroll
        for (int j = 0; j < 4; j++) mm[j] = Mb[n0 + tc + 16 * j];
#pragma unroll
        for (int i = 0; i < 4; i++)
#pragma unroll
            for (int j = 0; j < 4; j++) {
                float sv = s[i][j] * scale;
                s[i][j] = mm[j] ? sv : -1e30f;
            }

        // ---- online softmax: row max over the 16-lane tc-group ----
        float rm[4];
#pragma unroll
        for (int i = 0; i < 4; i++)
            rm[i] = fmaxf(fmaxf(s[i][0], s[i][1]), fmaxf(s[i][2], s[i][3]));
#pragma unroll
        for (int off = 8; off >= 1; off >>= 1)
#pragma unroll
            for (int i = 0; i < 4; i++)
                rm[i] = fmaxf(rm[i], __shfl_xor_sync(0xffffffffu, rm[i], off));

        float al[4];
#pragma unroll
        for (int i = 0; i < 4; i++) {
            float mnew = fmaxf(mrow[i], rm[i]);
            al[i] = __expf(mrow[i] - mnew);
            mrow[i] = mnew;
        }

        float psum[4];
#pragma unroll
        for (int i = 0; i < 4; i++) {
            float ps = 0.f;
#pragma unroll
            for (int j = 0; j < 4; j++) {
                float p = __expf(s[i][j] - mrow[i]);
                s[i][j] = p;
                ps += p;
            }
            psum[i] = ps;
        }
#pragma unroll
        for (int off = 8; off >= 1; off >>= 1)
#pragma unroll
            for (int i = 0; i < 4; i++)
                psum[i] += __shfl_xor_sync(0xffffffffu, psum[i], off);

#pragma unroll
        for (int i = 0; i < 4; i++) {
            lrow[i] = lrow[i] * al[i] + psum[i];
#pragma unroll
            for (int j = 0; j < 8; j++) O[i][j] *= al[i];
        }

        // P -> smem (writes conflict-free: 32 distinct banks per warp)
#pragma unroll
        for (int i = 0; i < 4; i++)
#pragma unroll
            for (int j = 0; j < 4; j++)
                sP[(tr * 4 + i) * PSTR + tc + 16 * j] = s[i][j];
        __syncthreads();

        // ---- O += P @ V (4x8 per thread), outer loop over n ----
#pragma unroll 2
        for (int n = 0; n < 64; n++) {
            float pv[4], vv[8];
#pragma unroll
            for (int i = 0; i < 4; i++) pv[i] = sP[(tr * 4 + i) * PSTR + n];
#pragma unroll
            for (int j = 0; j < 8; j++) vv[j] = sV[n * QSTR + tc + 16 * j];
#pragma unroll
            for (int i = 0; i < 4; i++)
#pragma unroll
                for (int j = 0; j < 8; j++) O[i][j] = fmaf(pv[i], vv[j], O[i][j]);
        }
    }

    // ---- epilogue: normalize and store ----
#pragma unroll
    for (int i = 0; i < 4; i++) {
        float inv = 1.0f / lrow[i];
#pragma unroll
        for (int j = 0; j < 8; j++)
            out[((long)b * SLQ + q0 + tr * 4 + i) * DIM + tc + 16 * j] = O[i][j] * inv;
    }
}

// ---------------------------------------------------------------------------
extern "C" void kernel_launch(void* const* d_in, const int* in_sizes, int n_in,
                              void* d_out, int out_size) {
    (void)in_sizes; (void)n_in; (void)out_size;
    const float* query = (const float*)d_in[0];
    const float* key   = (const float*)d_in[1];
    const float* value = (const float*)d_in[2];
    const float* Wq    = (const float*)d_in[3];
    const float* Wk    = (const float*)d_in[4];
    const float* Wv    = (const float*)d_in[5];
    const int*   mask  = (const int*)d_in[6];
    float* out = (float*)d_out;

    void *pq, *pk, *pv;
    cudaGetSymbolAddress(&pq, g_q);
    cudaGetSymbolAddress(&pk, g_k);
    cudaGetSymbolAddress(&pv, g_v);

    const int projSmem = (128 * 128 + 64 * QSTR) * (int)sizeof(float);   // 99,328 B
    const int attnSmem = (3 * 64 * QSTR + 64 * PSTR) * (int)sizeof(float); // 118,784 B
    cudaFuncSetAttribute(proj_kernel, cudaFuncAttributeMaxDynamicSharedMemorySize, projSmem);
    cudaFuncSetAttribute(attn_kernel, cudaFuncAttributeMaxDynamicSharedMemorySize, attnSmem);

    proj_kernel<<<NB * SLQ / 64, 256, projSmem>>>(query, Wq, (float*)pq);
    proj_kernel<<<NB * SLK / 64, 256, projSmem>>>(key,   Wk, (float*)pk);
    proj_kernel<<<NB * SLK / 64, 256, projSmem>>>(value, Wv, (float*)pv);
    attn_kernel<<<NB * SLQ / 64, 256, attnSmem>>>(mask, out);
}

// round 3
// speedup vs baseline: 2.2580x; 2.2580x over previous
#include <cuda_runtime.h>
#include <cuda_bf16.h>
#include <cstdint>

#define NB  8
#define SL  2048
#define DIM 128
#define BQ  128
#define BK  64
#define QS  132   // stride for Qhi/Qlo/Khi/Klo (≡4 mod 32)
#define VS  136   // stride for V (≡8 mod 32)
#define PS  68    // stride for P (≡4 mod 32)

// Projection outputs, pre-split for 3xTF32 (no allocs allowed in kernel_launch)
__device__ float          g_qhi[NB * SL * DIM];
__device__ __nv_bfloat16  g_qlo[NB * SL * DIM];
__device__ float          g_khi[NB * SL * DIM];
__device__ __nv_bfloat16  g_klo[NB * SL * DIM];
__device__ float          g_v  [NB * SL * DIM];

__device__ __forceinline__ uint32_t f2tf32(float x) {
    uint32_t u;
    asm("cvt.rna.tf32.f32 %0, %1;" : "=r"(u) : "f"(x));
    return u;
}

#define MMA8(C, A0, A1, A2, A3, B0, B1)                                      \
    asm volatile(                                                            \
        "mma.sync.aligned.m16n8k8.row.col.f32.tf32.tf32.f32 "                \
        "{%0,%1,%2,%3},{%4,%5,%6,%7},{%8,%9},{%0,%1,%2,%3};"                 \
        : "+f"(C[0]), "+f"(C[1]), "+f"(C[2]), "+f"(C[3])                     \
        : "r"(A0), "r"(A1), "r"(A2), "r"(A3), "r"(B0), "r"(B1))

// ---------------------------------------------------------------------------
// Projection: Y[R,128] = X[R,128] @ W[128,128], fp32 FFMA (exact path).
// If split: write tf32-rounded hi (fp32) + bf16 residual lo. Else plain fp32.
// ---------------------------------------------------------------------------
__global__ __launch_bounds__(256, 1)
void proj_kernel(const float* __restrict__ X, const float* __restrict__ W,
                 float* __restrict__ Yhi, __nv_bfloat16* __restrict__ Ylo,
                 int split) {
    extern __shared__ float sm[];
    float* sW = sm;                 // 128*128
    float* sX = sm + 128 * 128;     // 64*QS

    const int tid = threadIdx.x;
    const long r0 = (long)blockIdx.x * 64;

    for (int idx = tid; idx < 128 * 32; idx += 256) {
        int row = idx >> 5, k4 = (idx & 31) << 2;
        *(float4*)&sW[row * 128 + k4] = *(const float4*)&W[row * 128 + k4];
    }
    for (int idx = tid; idx < 64 * 32; idx += 256) {
        int row = idx >> 5, k4 = (idx & 31) << 2;
        *(float4*)&sX[row * QS + k4] = *(const float4*)&X[(r0 + row) * DIM + k4];
    }
    __syncthreads();

    const int tr = tid >> 4;
    const int tc = tid & 15;

    float acc[4][8];
#pragma unroll
    for (int i = 0; i < 4; i++)
#pragma unroll
        for (int j = 0; j < 8; j++) acc[i][j] = 0.f;

#pragma unroll 4
    for (int k = 0; k < 128; k++) {
        float xv[4], wv[8];
#pragma unroll
        for (int i = 0; i < 4; i++) xv[i] = sX[(tr * 4 + i) * QS + k];
#pragma unroll
        for (int j = 0; j < 8; j++) wv[j] = sW[k * 128 + tc + 16 * j];
#pragma unroll
        for (int i = 0; i < 4; i++)
#pragma unroll
            for (int j = 0; j < 8; j++) acc[i][j] = fmaf(xv[i], wv[j], acc[i][j]);
    }

#pragma unroll
    for (int i = 0; i < 4; i++)
#pragma unroll
        for (int j = 0; j < 8; j++) {
            long idx = (r0 + tr * 4 + i) * DIM + tc + 16 * j;
            float y = acc[i][j];
            if (split) {
                float hi = __uint_as_float(f2tf32(y));
                Yhi[idx] = hi;
                Ylo[idx] = __float2bfloat16(y - hi);
            } else {
                Yhi[idx] = y;
            }
        }
}

// ---------------------------------------------------------------------------
// Flash attention, tf32 mma.sync. CTA = 128 Q rows, 8 warps x 16 rows.
// S = QK^T with 3xTF32 (hi*hi + hi*lo + lo*hi); PV single tf32 (rna-rounded).
// ---------------------------------------------------------------------------
__global__ __launch_bounds__(256, 1)
void attn_kernel(const int* __restrict__ mask, float* __restrict__ out) {
    extern __shared__ float sm[];
    float*          sQhi = sm;                                  // 128*132
    float*          sKhi = sQhi + BQ * QS;                      // 64*132
    float*          sV   = sKhi + BK * QS;                      // 64*136
    float*          sP   = sV + BK * VS;                        // 128*68
    __nv_bfloat16*  sQlo = (__nv_bfloat16*)(sP + BQ * PS);      // 128*132
    __nv_bfloat16*  sKlo = sQlo + BQ * QS;                      // 64*132
    float*          sMsk = (float*)(sKlo + BK * QS);            // 64

    const int tid  = threadIdx.x;
    const int w    = tid >> 5;
    const int lane = tid & 31;
    const int g    = lane >> 2;   // group id (0..7)
    const int t    = lane & 3;    // thread-in-group (0..3)
    const int b    = blockIdx.x >> 4;
    const int q0   = (blockIdx.x & 15) << 7;

    const float*         Qhi = g_qhi + ((long)b * SL + q0) * DIM;
    const __nv_bfloat16* Qlo = g_qlo + ((long)b * SL + q0) * DIM;
    const float*         Khi = g_khi + (long)b * SL * DIM;
    const __nv_bfloat16* Klo = g_klo + (long)b * SL * DIM;
    const float*         Vg  = g_v   + (long)b * SL * DIM;
    const int*           Mb  = mask  + (long)b * SL;

    // Stage Q (hi fp32 + lo bf16) once
    for (int i = tid; i < BQ * 32; i += 256) {
        int r = i >> 5, c4 = (i & 31) << 2;
        *(float4*)&sQhi[r * QS + c4] = *(const float4*)&Qhi[r * DIM + c4];
        *(uint2*)&sQlo[r * QS + c4]  = *(const uint2*)&Qlo[r * DIM + c4];
    }

    const int qrow = (w << 4) + g;   // rows qrow and qrow+8 belong to this thread

    float o[16][4];
#pragma unroll
    for (int n = 0; n < 16; n++)
#pragma unroll
        for (int j = 0; j < 4; j++) o[n][j] = 0.f;
    float m0 = -1e30f, m1 = -1e30f, l0 = 0.f, l1 = 0.f;
    const float scale = 0.08838834764831845f;   // 1/sqrt(128)

    const float*          A0r = sQhi + qrow * QS;
    const float*          A1r = sQhi + (qrow + 8) * QS;
    const unsigned short* L0r = (const unsigned short*)(sQlo + qrow * QS);
    const unsigned short* L1r = (const unsigned short*)(sQlo + (qrow + 8) * QS);
    float* P0 = sP + qrow * PS;
    float* P1 = sP + (qrow + 8) * PS;

    for (int kt = 0; kt < SL / BK; kt++) {
        const int n0 = kt * BK;
        __syncthreads();   // prior iteration done with sK/sV (and Q visible, iter 0)
        for (int i = tid; i < BK * 32; i += 256) {
            int r = i >> 5, c4 = (i & 31) << 2;
            *(float4*)&sKhi[r * QS + c4] = *(const float4*)&Khi[(n0 + r) * DIM + c4];
            *(uint2*)&sKlo[r * QS + c4]  = *(const uint2*)&Klo[(n0 + r) * DIM + c4];
            float4 v4 = *(const float4*)&Vg[(n0 + r) * DIM + c4];
            v4.x = __uint_as_float(f2tf32(v4.x));
            v4.y = __uint_as_float(f2tf32(v4.y));
            v4.z = __uint_as_float(f2tf32(v4.z));
            v4.w = __uint_as_float(f2tf32(v4.w));
            *(float4*)&sV[r * VS + c4] = v4;
        }
        if (tid < BK) sMsk[tid] = Mb[n0 + tid] ? 0.f : -1e30f;
        __syncthreads();

        // ---- S = Q @ K^T, 3xTF32 ----
        float c[8][4];
#pragma unroll
        for (int n = 0; n < 8; n++)
#pragma unroll
            for (int j = 0; j < 4; j++) c[n][j] = 0.f;

#pragma unroll
        for (int kc = 0; kc < 16; kc++) {
            const int k0 = (kc << 3) + t;
            uint32_t a0 = __float_as_uint(A0r[k0]);
            uint32_t a1 = __float_as_uint(A1r[k0]);
            uint32_t a2 = __float_as_uint(A0r[k0 + 4]);
            uint32_t a3 = __float_as_uint(A1r[k0 + 4]);
            uint32_t q0l = ((uint32_t)L0r[k0]) << 16;
            uint32_t q1l = ((uint32_t)L1r[k0]) << 16;
            uint32_t q2l = ((uint32_t)L0r[k0 + 4]) << 16;
            uint32_t q3l = ((uint32_t)L1r[k0 + 4]) << 16;
#pragma unroll
            for (int nt = 0; nt < 8; nt++) {
                const float*          Bh = sKhi + (nt * 8 + g) * QS;
                const unsigned short* Bl = (const unsigned short*)(sKlo + (nt * 8 + g) * QS);
                uint32_t b0  = __float_as_uint(Bh[k0]);
                uint32_t b1  = __float_as_uint(Bh[k0 + 4]);
                uint32_t bl0 = ((uint32_t)Bl[k0]) << 16;
                uint32_t bl1 = ((uint32_t)Bl[k0 + 4]) << 16;
                MMA8(c[nt], a0, a1, a2, a3, b0, b1);
                MMA8(c[nt], a0, a1, a2, a3, bl0, bl1);
                MMA8(c[nt], q0l, q1l, q2l, q3l, b0, b1);
            }
        }

        // ---- scale + mask bias, row max (rows qrow -> state0, qrow+8 -> state1) ----
        float rx0 = -1e30f, rx1 = -1e30f;
#pragma unroll
        for (int nt = 0; nt < 8; nt++) {
            float bs0 = sMsk[nt * 8 + 2 * t];
            float bs1 = sMsk[nt * 8 + 2 * t + 1];
            c[nt][0] = fmaf(c[nt][0], scale, bs0);
            c[nt][1] = fmaf(c[nt][1], scale, bs1);
            c[nt][2] = fmaf(c[nt][2], scale, bs0);
            c[nt][3] = fmaf(c[nt][3], scale, bs1);
            rx0 = fmaxf(rx0, fmaxf(c[nt][0], c[nt][1]));
            rx1 = fmaxf(rx1, fmaxf(c[nt][2], c[nt][3]));
        }
        rx0 = fmaxf(rx0, __shfl_xor_sync(0xffffffffu, rx0, 1));
        rx0 = fmaxf(rx0, __shfl_xor_sync(0xffffffffu, rx0, 2));
        rx1 = fmaxf(rx1, __shfl_xor_sync(0xffffffffu, rx1, 1));
        rx1 = fmaxf(rx1, __shfl_xor_sync(0xffffffffu, rx1, 2));

        float mn0 = fmaxf(m0, rx0), mn1 = fmaxf(m1, rx1);
        float al0 = __expf(m0 - mn0), al1 = __expf(m1 - mn1);
        m0 = mn0; m1 = mn1;

        float ps0 = 0.f, ps1 = 0.f;
#pragma unroll
        for (int nt = 0; nt < 8; nt++) {
            c[nt][0] = __expf(c[nt][0] - m0);
            c[nt][1] = __expf(c[nt][1] - m0);
            c[nt][2] = __expf(c[nt][2] - m1);
            c[nt][3] = __expf(c[nt][3] - m1);
            ps0 += c[nt][0] + c[nt][1];
            ps1 += c[nt][2] + c[nt][3];
        }
        ps0 += __shfl_xor_sync(0xffffffffu, ps0, 1);
        ps0 += __shfl_xor_sync(0xffffffffu, ps0, 2);
        ps1 += __shfl_xor_sync(0xffffffffu, ps1, 1);
        ps1 += __shfl_xor_sync(0xffffffffu, ps1, 2);
        l0 = l0 * al0 + ps0;
        l1 = l1 * al1 + ps1;

        // rescale O
#pragma unroll
        for (int n = 0; n < 16; n++) {
            o[n][0] *= al0; o[n][1] *= al0;
            o[n][2] *= al1; o[n][3] *= al1;
        }

        // ---- P -> smem (warp-private rows), rna-rounded to tf32 ----
#pragma unroll
        for (int nt = 0; nt < 8; nt++) {
            float2 p01, p23;
            p01.x = __uint_as_float(f2tf32(c[nt][0]));
            p01.y = __uint_as_float(f2tf32(c[nt][1]));
            p23.x = __uint_as_float(f2tf32(c[nt][2]));
            p23.y = __uint_as_float(f2tf32(c[nt][3]));
            *(float2*)&P0[nt * 8 + 2 * t] = p01;
            *(float2*)&P1[nt * 8 + 2 * t] = p23;
        }
        __syncwarp();

        // ---- O += P @ V ----
#pragma unroll
        for (int kc = 0; kc < 8; kc++) {
            const int kk = (kc << 3) + t;
            uint32_t a0 = __float_as_uint(P0[kk]);
            uint32_t a1 = __float_as_uint(P1[kk]);
            uint32_t a2 = __float_as_uint(P0[kk + 4]);
            uint32_t a3 = __float_as_uint(P1[kk + 4]);
            const float* Vb0 = sV + kk * VS + g;
            const float* Vb1 = sV + (kk + 4) * VS + g;
#pragma unroll
            for (int nt = 0; nt < 16; nt++) {
                uint32_t b0 = __float_as_uint(Vb0[nt * 8]);
                uint32_t b1 = __float_as_uint(Vb1[nt * 8]);
                MMA8(o[nt], a0, a1, a2, a3, b0, b1);
            }
        }
    }

    // ---- epilogue ----
    float i0 = 1.f / l0, i1 = 1.f / l1;
    long base = ((long)b * SL + q0 + qrow) * DIM;
#pragma unroll
    for (int nt = 0; nt < 16; nt++) {
        float2 r0, r1;
        r0.x = o[nt][0] * i0; r0.y = o[nt][1] * i0;
        r1.x = o[nt][2] * i1; r1.y = o[nt][3] * i1;
        *(float2*)&out[base + nt * 8 + 2 * t] = r0;
        *(float2*)&out[base + 8 * DIM + nt * 8 + 2 * t] = r1;
    }
}

// ---------------------------------------------------------------------------
extern "C" void kernel_launch(void* const* d_in, const int* in_sizes, int n_in,
                              void* d_out, int out_size) {
    (void)in_sizes; (void)n_in; (void)out_size;
    const float* query = (const float*)d_in[0];
    const float* key   = (const float*)d_in[1];
    const float* value = (const float*)d_in[2];
    const float* Wq    = (const float*)d_in[3];
    const float* Wk    = (const float*)d_in[4];
    const float* Wv    = (const float*)d_in[5];
    const int*   mask  = (const int*)d_in[6];
    float* out = (float*)d_out;

    void *pqh, *pql, *pkh, *pkl, *pv;
    cudaGetSymbolAddress(&pqh, g_qhi);
    cudaGetSymbolAddress(&pql, g_qlo);
    cudaGetSymbolAddress(&pkh, g_khi);
    cudaGetSymbolAddress(&pkl, g_klo);
    cudaGetSymbolAddress(&pv,  g_v);

    const int projSmem = (128 * 128 + 64 * QS) * (int)sizeof(float);
    const int attnSmem = (BQ * QS + BK * QS + BK * VS + BQ * PS) * 4
                       + (BQ * QS + BK * QS) * 2 + BK * 4;
    cudaFuncSetAttribute(proj_kernel, cudaFuncAttributeMaxDynamicSharedMemorySize, projSmem);
    cudaFuncSetAttribute(attn_kernel, cudaFuncAttributeMaxDynamicSharedMemorySize, attnSmem);

    proj_kernel<<<NB * SL / 64, 256, projSmem>>>(query, Wq, (float*)pqh,
                                                 (__nv_bfloat16*)pql, 1);
    proj_kernel<<<NB * SL / 64, 256, projSmem>>>(key, Wk, (float*)pkh,
                                                 (__nv_bfloat16*)pkl, 1);
    proj_kernel<<<NB * SL / 64, 256, projSmem>>>(value, Wv, (float*)pv, nullptr, 0);
    attn_kernel<<<NB * SL / BQ, 256, attnSmem>>>(mask, out);
}

// round 4
// speedup vs baseline: 3.3952x; 1.5036x over previous
#include <cuda_runtime.h>
#include <cuda_fp16.h>
#include <cstdint>

#define NB  8
#define SL  2048
#define DIM 128
#define BQ  128
#define BK  64
#define NT  (SL / BK)     // 32 K-tiles

// smem byte strides
#define RQ  288           // Q/K row: 128 halves (256B) + 32B pad  -> banks 8g+2t
#define RV  160           // Vt row: 64 halves (128B) + 32B pad

// smem byte offsets (all 16B aligned). Total 188,928 B.
#define OQH 0
#define OQL (OQH + BQ * RQ)            // 36864
#define OKH (OQL + BQ * RQ)            // 73728  (2 bufs x 64*288)
#define OKL (OKH + 2 * BK * RQ)        // 110592
#define OVT (OKL + 2 * BK * RQ)        // 147456 (2 bufs x 128*160)
#define OMK (OVT + 2 * DIM * RV)       // 188416 (2 x 256B)
#define SMEM_ATTN (OMK + 2 * 256)      // 188928

// Projected tensors, pre-split fp16 hi/lo, pair-permuted columns; V transposed.
__device__ __half g_qhi[NB * SL * DIM];
__device__ __half g_qlo[NB * SL * DIM];
__device__ __half g_khi[NB * SL * DIM];
__device__ __half g_klo[NB * SL * DIM];
__device__ __half g_vt [NB * DIM * SL];   // [b][dim][key], key pair-permuted

__device__ __forceinline__ uint32_t h2u(__half2 h) {
    return *reinterpret_cast<uint32_t*>(&h);
}
__device__ __forceinline__ void cpa16(uint32_t saddr, const void* gaddr) {
    asm volatile("cp.async.ca.shared.global [%0], [%1], 16;\n"
                 :: "r"(saddr), "l"(gaddr));
}
__device__ __forceinline__ void cpa_commit() {
    asm volatile("cp.async.commit_group;\n" ::: "memory");
}

#define MMA16(C, A0, A1, A2, A3, B0, B1)                                     \
    asm volatile(                                                            \
        "mma.sync.aligned.m16n8k16.row.col.f32.f16.f16.f32 "                 \
        "{%0,%1,%2,%3},{%4,%5,%6,%7},{%8,%9},{%0,%1,%2,%3};"                 \
        : "+f"(C[0]), "+f"(C[1]), "+f"(C[2]), "+f"(C[3])                     \
        : "r"(A0), "r"(A1), "r"(A2), "r"(A3), "r"(B0), "r"(B1))

// Pair permutation within a 16-col chunk: pair p (cols 2p,2p+1) -> word w.
// words [0..7] hold pairs [0,4,1,5,2,6,3,7]  (w = p<4 ? 2p : 2(p-4)+1)
__host__ __device__ __forceinline__ int permloc(int loc) {   // loc 0..15 -> loc'
    int p = loc >> 1, h = loc & 1;
    int w = (p < 4) ? (2 * p) : (2 * (p - 4) + 1);
    return 2 * w + h;
}

// ---------------------------------------------------------------------------
// Q/K projection: Y = X @ W (fp32 FFMA), output half hi + half lo, columns
// pair-permuted within 16-col chunks (matches attn smem fragment layout).
// ---------------------------------------------------------------------------
__global__ __launch_bounds__(256, 1)
void proj_qk(const float* __restrict__ X, const float* __restrict__ W,
             __half* __restrict__ Yh, __half* __restrict__ Yl) {
    extern __shared__ float sm[];
    float* sW = sm;
    float* sX = sm + 128 * 128;   // stride 132

    const int tid = threadIdx.x;
    const long r0 = (long)blockIdx.x * 64;

    for (int idx = tid; idx < 128 * 32; idx += 256) {
        int row = idx >> 5, k4 = (idx & 31) << 2;
        *(float4*)&sW[row * 128 + k4] = *(const float4*)&W[row * 128 + k4];
    }
    for (int idx = tid; idx < 64 * 32; idx += 256) {
        int row = idx >> 5, k4 = (idx & 31) << 2;
        *(float4*)&sX[row * 132 + k4] = *(const float4*)&X[(r0 + row) * DIM + k4];
    }
    __syncthreads();

    const int tr = tid >> 4;
    const int tc = tid & 15;
    const int locp = permloc(tc);

    float acc[4][8];
#pragma unroll
    for (int i = 0; i < 4; i++)
#pragma unroll
        for (int j = 0; j < 8; j++) acc[i][j] = 0.f;

#pragma unroll 4
    for (int k = 0; k < 128; k++) {
        float xv[4], wv[8];
#pragma unroll
        for (int i = 0; i < 4; i++) xv[i] = sX[(tr * 4 + i) * 132 + k];
#pragma unroll
        for (int j = 0; j < 8; j++) wv[j] = sW[k * 128 + tc + 16 * j];
#pragma unroll
        for (int i = 0; i < 4; i++)
#pragma unroll
            for (int j = 0; j < 8; j++) acc[i][j] = fmaf(xv[i], wv[j], acc[i][j]);
    }

#pragma unroll
    for (int i = 0; i < 4; i++)
#pragma unroll
        for (int j = 0; j < 8; j++) {
            long idx = (r0 + tr * 4 + i) * DIM + 16 * j + locp;
            float y  = acc[i][j];
            __half hi = __float2half_rn(y);
            Yh[idx] = hi;
            Yl[idx] = __float2half_rn(y - __half2float(hi));
        }
}

// ---------------------------------------------------------------------------
// V projection: Y = X @ Wv (fp32 FFMA) -> half, written TRANSPOSED into
// g_vt[b][dim][key] with keys pair-permuted. Coalesced 128B row writes.
// ---------------------------------------------------------------------------
__global__ __launch_bounds__(256, 1)
void proj_v(const float* __restrict__ X, const float* __restrict__ W) {
    extern __shared__ float sm[];
    float* sW = sm;
    float* sX = sm + 128 * 128;
    __half* sT = (__half*)sm;     // reused after compute: 64 x 136 halves

    const int tid = threadIdx.x;
    const long r0 = (long)blockIdx.x * 64;
    const int bb  = (int)(r0 >> 11);
    const int k0  = (int)(r0 & 2047);

    for (int idx = tid; idx < 128 * 32; idx += 256) {
        int row = idx >> 5, k4 = (idx & 31) << 2;
        *(float4*)&sW[row * 128 + k4] = *(const float4*)&W[row * 128 + k4];
    }
    for (int idx = tid; idx < 64 * 32; idx += 256) {
        int row = idx >> 5, k4 = (idx & 31) << 2;
        *(float4*)&sX[row * 132 + k4] = *(const float4*)&X[(r0 + row) * DIM + k4];
    }
    __syncthreads();

    const int tr = tid >> 4;
    const int tc = tid & 15;

    float acc[4][8];
#pragma unroll
    for (int i = 0; i < 4; i++)
#pragma unroll
        for (int j = 0; j < 8; j++) acc[i][j] = 0.f;

#pragma unroll 4
    for (int k = 0; k < 128; k++) {
        float xv[4], wv[8];
#pragma unroll
        for (int i = 0; i < 4; i++) xv[i] = sX[(tr * 4 + i) * 132 + k];
#pragma unroll
        for (int j = 0; j < 8; j++) wv[j] = sW[k * 128 + tc + 16 * j];
#pragma unroll
        for (int i = 0; i < 4; i++)
#pragma unroll
            for (int j = 0; j < 8; j++) acc[i][j] = fmaf(xv[i], wv[j], acc[i][j]);
    }
    __syncthreads();   // done reading sW/sX; reuse as sT

#pragma unroll
    for (int i = 0; i < 4; i++)
#pragma unroll
        for (int j = 0; j < 8; j++)
            sT[(tr * 4 + i) * 136 + tc + 16 * j] = __float2half_rn(acc[i][j]);
    __syncthreads();

    // Transposed, pair-permuted write: warp w -> dims w*16..w*16+15,
    // lane l -> key-pair p=l (keys 2l, 2l+1) -> permuted word position.
    const int w    = tid >> 5;
    const int lane = tid & 31;
    const int pc   = lane >> 3;        // 16-key chunk 0..3
    const int pl   = lane & 7;         // pair within chunk
    const int wd   = (pl < 4) ? (2 * pl) : (2 * (pl - 4) + 1);
    const int dstk = k0 + pc * 16 + 2 * wd;
#pragma unroll
    for (int m = 0; m < 16; m++) {
        int d = w * 16 + m;
        __half2 h2 = __halves2half2(sT[(2 * lane) * 136 + d],
                                    (__half)sT[(2 * lane + 1) * 136 + d]);
        *(uint32_t*)&g_vt[((long)bb * DIM + d) * SL + dstk] = h2u(h2);
    }
}

// ---------------------------------------------------------------------------
// Flash attention, fp16 hi/lo mma.sync m16n8k16, cp.async double buffer.
// CTA = 128 Q rows, 8 warps x 16 rows. P passes S->PV in registers.
// ---------------------------------------------------------------------------
__global__ __launch_bounds__(256, 1)
void attn_kernel(const int* __restrict__ mask, float* __restrict__ out) {
    extern __shared__ char smem[];
    const uint32_t sb = (uint32_t)__cvta_generic_to_shared(smem);

    const int tid  = threadIdx.x;
    const int w    = tid >> 5;
    const int lane = tid & 31;
    const int g    = lane >> 2;
    const int t    = lane & 3;
    const int b    = blockIdx.x >> 4;
    const int q0   = (blockIdx.x & 15) << 7;

    const __half* gqh = g_qhi + ((long)b * SL + q0) * DIM;
    const __half* gql = g_qlo + ((long)b * SL + q0) * DIM;
    const __half* gkh = g_khi + (long)b * SL * DIM;
    const __half* gkl = g_klo + (long)b * SL * DIM;
    const __half* gvt = g_vt  + (long)b * DIM * SL;
    const int*    gmk = mask  + (long)b * SL;

    // ---- issue Q (hi+lo) + tile0 as group 0; tile1 as group 1 ----
    for (int i = tid; i < 4096; i += 256) {
        if (i < 2048) {
            int r = i >> 4, c = i & 15;
            cpa16(sb + OQH + r * RQ + c * 16, gqh + r * DIM + c * 8);
        } else {
            int j = i - 2048, r = j >> 4, c = j & 15;
            cpa16(sb + OQL + r * RQ + c * 16, gql + r * DIM + c * 8);
        }
    }
#define ISSUE_TILE(kt, s)                                                     \
    {                                                                         \
        const int n0_ = (kt) * BK;                                            \
        for (int i = tid; i < 3088; i += 256) {                               \
            if (i < 1024) {                                                   \
                int r = i >> 4, c = i & 15;                                   \
                cpa16(sb + OKH + (s) * (BK * RQ) + r * RQ + c * 16,           \
                      gkh + (long)(n0_ + r) * DIM + c * 8);                   \
            } else if (i < 2048) {                                            \
                int j = i - 1024, r = j >> 4, c = j & 15;                     \
                cpa16(sb + OKL + (s) * (BK * RQ) + r * RQ + c * 16,           \
                      gkl + (long)(n0_ + r) * DIM + c * 8);                   \
            } else if (i < 3072) {                                            \
                int j = i - 2048, r = j >> 3, c = j & 7;                      \
                cpa16(sb + OVT + (s) * (DIM * RV) + r * RV + c * 16,          \
                      gvt + (long)r * SL + n0_ + c * 8);                      \
            } else {                                                          \
                int j = i - 3072;                                             \
                cpa16(sb + OMK + (s) * 256 + j * 16, gmk + n0_ + j * 4);      \
            }                                                                 \
        }                                                                     \
    }
    ISSUE_TILE(0, 0);
    cpa_commit();
    ISSUE_TILE(1, 1);
    cpa_commit();

    const int qrow = (w << 4) + g;
    const char* qh0 = smem + OQH + qrow * RQ;
    const char* qh1 = qh0 + 8 * RQ;
    const char* ql0 = smem + OQL + qrow * RQ;
    const char* ql1 = ql0 + 8 * RQ;

    float o[16][4];
#pragma unroll
    for (int n = 0; n < 16; n++)
#pragma unroll
        for (int j = 0; j < 4; j++) o[n][j] = 0.f;
    float m0 = -1e30f, m1 = -1e30f, l0 = 0.f, l1 = 0.f;
    const float scale = 0.08838834764831845f;

    for (int kt = 0; kt < NT; kt++) {
        const int s = kt & 1;
        if (kt < NT - 1)
            asm volatile("cp.async.wait_group 1;\n" ::: "memory");
        else
            asm volatile("cp.async.wait_group 0;\n" ::: "memory");
        __syncthreads();

        const char* kh = smem + OKH + s * (BK * RQ) + g * RQ;
        const char* kl = smem + OKL + s * (BK * RQ) + g * RQ;
        const char* vb = smem + OVT + s * (DIM * RV) + g * RV;
        const int*  mk = (const int*)(smem + OMK + s * 256);

        // ---- S = Q K^T : hi*hi + hi*lo + lo*hi ----
        float c[8][4];
#pragma unroll
        for (int n = 0; n < 8; n++)
#pragma unroll
            for (int j = 0; j < 4; j++) c[n][j] = 0.f;

#pragma unroll
        for (int kc = 0; kc < 8; kc++) {
            const int off = kc * 32 + t * 8;
            uint2 h0 = *(const uint2*)(qh0 + off);   // {a0, a2}
            uint2 h1 = *(const uint2*)(qh1 + off);   // {a1, a3}
            uint2 ll0 = *(const uint2*)(ql0 + off);
            uint2 ll1 = *(const uint2*)(ql1 + off);
#pragma unroll
            for (int nt = 0; nt < 8; nt++) {
                uint2 bh = *(const uint2*)(kh + nt * (8 * RQ) + off);
                uint2 bl = *(const uint2*)(kl + nt * (8 * RQ) + off);
                MMA16(c[nt], h0.x, h1.x, h0.y, h1.y, bh.x, bh.y);
                MMA16(c[nt], h0.x, h1.x, h0.y, h1.y, bl.x, bl.y);
                MMA16(c[nt], ll0.x, ll1.x, ll0.y, ll1.y, bh.x, bh.y);
            }
        }

        // ---- scale + mask bias + online softmax ----
        float rx0 = -1e30f, rx1 = -1e30f;
#pragma unroll
        for (int nt = 0; nt < 8; nt++) {
            float bs0 = mk[nt * 8 + 2 * t]     ? 0.f : -1e30f;
            float bs1 = mk[nt * 8 + 2 * t + 1] ? 0.f : -1e30f;
            c[nt][0] = fmaf(c[nt][0], scale, bs0);
            c[nt][1] = fmaf(c[nt][1], scale, bs1);
            c[nt][2] = fmaf(c[nt][2], scale, bs0);
            c[nt][3] = fmaf(c[nt][3], scale, bs1);
            rx0 = fmaxf(rx0, fmaxf(c[nt][0], c[nt][1]));
            rx1 = fmaxf(rx1, fmaxf(c[nt][2], c[nt][3]));
        }
        rx0 = fmaxf(rx0, __shfl_xor_sync(0xffffffffu, rx0, 1));
        rx0 = fmaxf(rx0, __shfl_xor_sync(0xffffffffu, rx0, 2));
        rx1 = fmaxf(rx1, __shfl_xor_sync(0xffffffffu, rx1, 1));
        rx1 = fmaxf(rx1, __shfl_xor_sync(0xffffffffu, rx1, 2));

        float mn0 = fmaxf(m0, rx0), mn1 = fmaxf(m1, rx1);
        float al0 = __expf(m0 - mn0), al1 = __expf(m1 - mn1);
        m0 = mn0; m1 = mn1;

        float ps0 = 0.f, ps1 = 0.f;
#pragma unroll
        for (int nt = 0; nt < 8; nt++) {
            c[nt][0] = __expf(c[nt][0] - m0);
            c[nt][1] = __expf(c[nt][1] - m0);
            c[nt][2] = __expf(c[nt][2] - m1);
            c[nt][3] = __expf(c[nt][3] - m1);
            ps0 += c[nt][0] + c[nt][1];
            ps1 += c[nt][2] + c[nt][3];
        }
        ps0 += __shfl_xor_sync(0xffffffffu, ps0, 1);
        ps0 += __shfl_xor_sync(0xffffffffu, ps0, 2);
        ps1 += __shfl_xor_sync(0xffffffffu, ps1, 1);
        ps1 += __shfl_xor_sync(0xffffffffu, ps1, 2);
        l0 = l0 * al0 + ps0;
        l1 = l1 * al1 + ps1;

#pragma unroll
        for (int n = 0; n < 16; n++) {
            o[n][0] *= al0; o[n][1] *= al0;
            o[n][2] *= al1; o[n][3] *= al1;
        }

        // ---- O += P V : P hi/lo straight from registers (C-frag == A-frag) ----
#pragma unroll
        for (int kc = 0; kc < 4; kc++) {
            float2 f0 = make_float2(c[2 * kc][0],     c[2 * kc][1]);
            float2 f1 = make_float2(c[2 * kc][2],     c[2 * kc][3]);
            float2 f2 = make_float2(c[2 * kc + 1][0], c[2 * kc + 1][1]);
            float2 f3 = make_float2(c[2 * kc + 1][2], c[2 * kc + 1][3]);
            __half2 ah0 = __float22half2_rn(f0);
            __half2 ah1 = __float22half2_rn(f1);
            __half2 ah2 = __float22half2_rn(f2);
            __half2 ah3 = __float22half2_rn(f3);
            float2 r0 = __half22float2(ah0), r1 = __half22float2(ah1);
            float2 r2 = __half22float2(ah2), r3 = __half22float2(ah3);
            __half2 al_0 = __float22half2_rn(make_float2(f0.x - r0.x, f0.y - r0.y));
            __half2 al_1 = __float22half2_rn(make_float2(f1.x - r1.x, f1.y - r1.y));
            __half2 al_2 = __float22half2_rn(make_float2(f2.x - r2.x, f2.y - r2.y));
            __half2 al_3 = __float22half2_rn(make_float2(f3.x - r3.x, f3.y - r3.y));
            uint32_t Ah0 = h2u(ah0), Ah1 = h2u(ah1), Ah2 = h2u(ah2), Ah3 = h2u(ah3);
            uint32_t Al0 = h2u(al_0), Al1 = h2u(al_1), Al2 = h2u(al_2), Al3 = h2u(al_3);
            const int off = kc * 32 + t * 8;
#pragma unroll
            for (int nt = 0; nt < 16; nt++) {
                uint2 bv = *(const uint2*)(vb + nt * (8 * RV) + off);
                MMA16(o[nt], Ah0, Ah1, Ah2, Ah3, bv.x, bv.y);
                MMA16(o[nt], Al0, Al1, Al2, Al3, bv.x, bv.y);
            }
        }

        __syncthreads();
        if (kt + 2 < NT) {
            ISSUE_TILE(kt + 2, s);
            cpa_commit();
        }
    }

    // ---- epilogue ----
    float i0 = 1.f / l0, i1 = 1.f / l1;
    long base = ((long)b * SL + q0 + qrow) * DIM;
#pragma unroll
    for (int nt = 0; nt < 16; nt++) {
        float2 r0, r1;
        r0.x = o[nt][0] * i0; r0.y = o[nt][1] * i0;
        r1.x = o[nt][2] * i1; r1.y = o[nt][3] * i1;
        *(float2*)&out[base + nt * 8 + 2 * t] = r0;
        *(float2*)&out[base + 8 * DIM + nt * 8 + 2 * t] = r1;
    }
}

// ---------------------------------------------------------------------------
extern "C" void kernel_launch(void* const* d_in, const int* in_sizes, int n_in,
                              void* d_out, int out_size) {
    (void)in_sizes; (void)n_in; (void)out_size;
    const float* query = (const float*)d_in[0];
    const float* key   = (const float*)d_in[1];
    const float* value = (const float*)d_in[2];
    const float* Wq    = (const float*)d_in[3];
    const float* Wk    = (const float*)d_in[4];
    const float* Wv    = (const float*)d_in[5];
    const int*   mask  = (const int*)d_in[6];
    float* out = (float*)d_out;

    void *pqh, *pql, *pkh, *pkl;
    cudaGetSymbolAddress(&pqh, g_qhi);
    cudaGetSymbolAddress(&pql, g_qlo);
    cudaGetSymbolAddress(&pkh, g_khi);
    cudaGetSymbolAddress(&pkl, g_klo);

    const int projSmem = (128 * 128 + 64 * 132) * (int)sizeof(float);
    cudaFuncSetAttribute(proj_qk, cudaFuncAttributeMaxDynamicSharedMemorySize, projSmem);
    cudaFuncSetAttribute(proj_v,  cudaFuncAttributeMaxDynamicSharedMemorySize, projSmem);
    cudaFuncSetAttribute(attn_kernel, cudaFuncAttributeMaxDynamicSharedMemorySize, SMEM_ATTN);

    proj_qk<<<NB * SL / 64, 256, projSmem>>>(query, Wq, (__half*)pqh, (__half*)pql);
    proj_qk<<<NB * SL / 64, 256, projSmem>>>(key,   Wk, (__half*)pkh, (__half*)pkl);
    proj_v <<<NB * SL / 64, 256, projSmem>>>(value, Wv);
    attn_kernel<<<NB * SL / BQ, 256, SMEM_ATTN>>>(mask, out);
}

// round 7
// speedup vs baseline: 3.8870x; 1.1449x over previous
#include <cuda_runtime.h>
#include <cuda_fp16.h>
#include <cstdint>

#define NB  8
#define SL  2048
#define DIM 128
#define BQ  128
#define BK  64
#define NT  (SL / BK)     // 32 K-tiles

// smem byte strides
#define RQ  288           // Q/K row: 128 halves (256B) + 32B pad  -> banks 8g+2t
#define RV  160           // Vt row: 64 halves (128B) + 32B pad

// smem byte offsets (all 16B aligned). Total 152,064 B -> 1 CTA/SM.
#define OQH 0
#define OKH (OQH + BQ * RQ)            // 36864  (2 bufs x 64*288)
#define OKL (OKH + 2 * BK * RQ)        // 73728
#define OVT (OKL + 2 * BK * RQ)        // 110592 (2 bufs x 128*160)
#define OMK (OVT + 2 * DIM * RV)       // 151552 (2 x 256B)
#define SMEM_ATTN (OMK + 2 * 256)      // 152064

// Projected tensors: Q hi-only; K hi+lo fp16 split; V transposed half.
// Columns pair-permuted to match MMA fragment layout.
__device__ __half g_qhi[NB * SL * DIM];
__device__ __half g_khi[NB * SL * DIM];
__device__ __half g_klo[NB * SL * DIM];
__device__ __half g_vt [NB * DIM * SL];   // [b][dim][key], key pair-permuted

__device__ __forceinline__ uint32_t h2u(__half2 h) {
    return *reinterpret_cast<uint32_t*>(&h);
}
__device__ __forceinline__ void cpa16(uint32_t saddr, const void* gaddr) {
    asm volatile("cp.async.ca.shared.global [%0], [%1], 16;\n"
                 :: "r"(saddr), "l"(gaddr));
}
__device__ __forceinline__ void cpa_commit() {
    asm volatile("cp.async.commit_group;\n" ::: "memory");
}

#define MMA16(C, A0, A1, A2, A3, B0, B1)                                     \
    asm volatile(                                                            \
        "mma.sync.aligned.m16n8k16.row.col.f32.f16.f16.f32 "                 \
        "{%0,%1,%2,%3},{%4,%5,%6,%7},{%8,%9},{%0,%1,%2,%3};"                 \
        : "+f"(C[0]), "+f"(C[1]), "+f"(C[2]), "+f"(C[3])                     \
        : "r"(A0), "r"(A1), "r"(A2), "r"(A3), "r"(B0), "r"(B1))

// Pair permutation within a 16-col chunk: pair p (cols 2p,2p+1) -> word w.
__host__ __device__ __forceinline__ int permloc(int loc) {
    int p = loc >> 1, h = loc & 1;
    int w = (p < 4) ? (2 * p) : (2 * (p - 4) + 1);
    return 2 * w + h;
}

// ---------------------------------------------------------------------------
// Fused projections: sel = blockIdx.x>>8 picks {Q, K, V}.
//   Q: hi fp16, pair-permuted.   K: hi+lo fp16, pair-permuted.
//   V: half, transposed to g_vt[b][dim][key], keys pair-permuted.
// 2 CTAs/SM (99 KB smem each).
// ---------------------------------------------------------------------------
__global__ __launch_bounds__(256, 2)
void proj_all(const float* __restrict__ Xq, const float* __restrict__ Xk,
              const float* __restrict__ Xv, const float* __restrict__ Wq,
              const float* __restrict__ Wk, const float* __restrict__ Wv) {
    extern __shared__ float sm[];
    float* sW = sm;               // 128*128
    float* sX = sm + 128 * 128;   // 64 rows, stride 132
    __half* sT = (__half*)sm;     // V path reuse: 64 x 136 halves

    const int sel = blockIdx.x >> 8;
    const int blk = blockIdx.x & 255;
    const float* X = (sel == 0) ? Xq : (sel == 1) ? Xk : Xv;
    const float* W = (sel == 0) ? Wq : (sel == 1) ? Wk : Wv;

    const int tid = threadIdx.x;
    const long r0 = (long)blk * 64;

    for (int idx = tid; idx < 128 * 32; idx += 256) {
        int row = idx >> 5, k4 = (idx & 31) << 2;
        *(float4*)&sW[row * 128 + k4] = *(const float4*)&W[row * 128 + k4];
    }
    for (int idx = tid; idx < 64 * 32; idx += 256) {
        int row = idx >> 5, k4 = (idx & 31) << 2;
        *(float4*)&sX[row * 132 + k4] = *(const float4*)&X[(r0 + row) * DIM + k4];
    }
    __syncthreads();

    const int tr = tid >> 4;
    const int tc = tid & 15;

    float acc[4][8];
#pragma unroll
    for (int i = 0; i < 4; i++)
#pragma unroll
        for (int j = 0; j < 8; j++) acc[i][j] = 0.f;

#pragma unroll 4
    for (int k = 0; k < 128; k++) {
        float xv[4], wv[8];
#pragma unroll
        for (int i = 0; i < 4; i++) xv[i] = sX[(tr * 4 + i) * 132 + k];
#pragma unroll
        for (int j = 0; j < 8; j++) wv[j] = sW[k * 128 + tc + 16 * j];
#pragma unroll
        for (int i = 0; i < 4; i++)
#pragma unroll
            for (int j = 0; j < 8; j++) acc[i][j] = fmaf(xv[i], wv[j], acc[i][j]);
    }

    if (sel < 2) {
        const int locp = permloc(tc);
#pragma unroll
        for (int i = 0; i < 4; i++)
#pragma unroll
            for (int j = 0; j < 8; j++) {
                long idx = (r0 + tr * 4 + i) * DIM + 16 * j + locp;
                float y  = acc[i][j];
                __half hi = __float2half_rn(y);
                if (sel == 0) {
                    g_qhi[idx] = hi;
                } else {
                    g_khi[idx] = hi;
                    g_klo[idx] = __float2half_rn(y - __half2float(hi));
                }
            }
    } else {
        const int bb = (int)(r0 >> 11);
        const int k0 = (int)(r0 & 2047);
        __syncthreads();   // done reading sW/sX; reuse as sT
#pragma unroll
        for (int i = 0; i < 4; i++)
#pragma unroll
            for (int j = 0; j < 8; j++)
                sT[(tr * 4 + i) * 136 + tc + 16 * j] = __float2half_rn(acc[i][j]);
        __syncthreads();

        const int w    = tid >> 5;
        const int lane = tid & 31;
        const int pc   = lane >> 3;
        const int pl   = lane & 7;
        const int wd   = (pl < 4) ? (2 * pl) : (2 * (pl - 4) + 1);
        const int dstk = k0 + pc * 16 + 2 * wd;
#pragma unroll
        for (int m = 0; m < 16; m++) {
            int d = w * 16 + m;
            __half2 h2 = __halves2half2(sT[(2 * lane) * 136 + d],
                                        (__half)sT[(2 * lane + 1) * 136 + d]);
            *(uint32_t*)&g_vt[((long)bb * DIM + d) * SL + dstk] = h2u(h2);
        }
    }
}

// ---------------------------------------------------------------------------
// Flash attention, fp16 mma.sync m16n8k16, cp.async double buffer.
// S = Qhi*(Khi+Klo), pass-split MMA scheduling; P hi/lo in registers.
// ---------------------------------------------------------------------------
__global__ __launch_bounds__(256, 1)
void attn_kernel(const int* __restrict__ mask, float* __restrict__ out) {
    extern __shared__ char smem[];
    const uint32_t sb = (uint32_t)__cvta_generic_to_shared(smem);

    const int tid  = threadIdx.x;
    const int w    = tid >> 5;
    const int lane = tid & 31;
    const int g    = lane >> 2;
    const int t    = lane & 3;
    const int b    = blockIdx.x >> 4;
    const int q0   = (blockIdx.x & 15) << 7;

    const __half* gqh = g_qhi + ((long)b * SL + q0) * DIM;
    const __half* gkh = g_khi + (long)b * SL * DIM;
    const __half* gkl = g_klo + (long)b * SL * DIM;
    const __half* gvt = g_vt  + (long)b * DIM * SL;
    const int*    gmk = mask  + (long)b * SL;

    // ---- issue Q(hi) + tile0 as group 0; tile1 as group 1 ----
    for (int i = tid; i < 2048; i += 256) {
        int r = i >> 4, c = i & 15;
        cpa16(sb + OQH + r * RQ + c * 16, gqh + r * DIM + c * 8);
    }
#define ISSUE_TILE(kt, s)                                                     \
    {                                                                         \
        const int n0_ = (kt) * BK;                                            \
        for (int i = tid; i < 3088; i += 256) {                               \
            if (i < 1024) {                                                   \
                int r = i >> 4, c = i & 15;                                   \
                cpa16(sb + OKH + (s) * (BK * RQ) + r * RQ + c * 16,           \
                      gkh + (long)(n0_ + r) * DIM + c * 8);                   \
            } else if (i < 2048) {                                            \
                int j = i - 1024, r = j >> 4, c = j & 15;                     \
                cpa16(sb + OKL + (s) * (BK * RQ) + r * RQ + c * 16,           \
                      gkl + (long)(n0_ + r) * DIM + c * 8);                   \
            } else if (i < 3072) {                                            \
                int j = i - 2048, r = j >> 3, c = j & 7;                      \
                cpa16(sb + OVT + (s) * (DIM * RV) + r * RV + c * 16,          \
                      gvt + (long)r * SL + n0_ + c * 8);                      \
            } else {                                                          \
                int j = i - 3072;                                             \
                cpa16(sb + OMK + (s) * 256 + j * 16, gmk + n0_ + j * 4);      \
            }                                                                 \
        }                                                                     \
    }
    ISSUE_TILE(0, 0);
    cpa_commit();
    ISSUE_TILE(1, 1);
    cpa_commit();

    const int qrow = (w << 4) + g;
    const char* qh0 = smem + OQH + qrow * RQ;
    const char* qh1 = qh0 + 8 * RQ;

    float o[16][4];
#pragma unroll
    for (int n = 0; n < 16; n++)
#pragma unroll
        for (int j = 0; j < 4; j++) o[n][j] = 0.f;
    float m0 = -1e30f, m1 = -1e30f, l0 = 0.f, l1 = 0.f;
    const float scale = 0.08838834764831845f;

    for (int kt = 0; kt < NT; kt++) {
        const int s = kt & 1;
        if (kt < NT - 1)
            asm volatile("cp.async.wait_group 1;\n" ::: "memory");
        else
            asm volatile("cp.async.wait_group 0;\n" ::: "memory");
        __syncthreads();

        const char* kh = smem + OKH + s * (BK * RQ) + g * RQ;
        const char* kl = smem + OKL + s * (BK * RQ) + g * RQ;
        const char* vb = smem + OVT + s * (DIM * RV) + g * RV;
        const int*  mk = (const int*)(smem + OMK + s * 256);

        // ---- S = Qhi*(Khi + Klo), pass-split over nt for ILP ----
        float c[8][4];
#pragma unroll
        for (int n = 0; n < 8; n++)
#pragma unroll
            for (int j = 0; j < 4; j++) c[n][j] = 0.f;

#pragma unroll
        for (int kc = 0; kc < 8; kc++) {
            const int off = kc * 32 + t * 8;
            uint2 h0 = *(const uint2*)(qh0 + off);   // {a0, a2}
            uint2 h1 = *(const uint2*)(qh1 + off);   // {a1, a3}
#pragma unroll
            for (int nt = 0; nt < 8; nt++) {
                uint2 bh = *(const uint2*)(kh + nt * (8 * RQ) + off);
                MMA16(c[nt], h0.x, h1.x, h0.y, h1.y, bh.x, bh.y);
            }
#pragma unroll
            for (int nt = 0; nt < 8; nt++) {
                uint2 bl = *(const uint2*)(kl + nt * (8 * RQ) + off);
                MMA16(c[nt], h0.x, h1.x, h0.y, h1.y, bl.x, bl.y);
            }
        }

        // ---- scale + mask bias + online softmax ----
        float rx0 = -1e30f, rx1 = -1e30f;
#pragma unroll
        for (int nt = 0; nt < 8; nt++) {
            float bs0 = mk[nt * 8 + 2 * t]     ? 0.f : -1e30f;
            float bs1 = mk[nt * 8 + 2 * t + 1] ? 0.f : -1e30f;
            c[nt][0] = fmaf(c[nt][0], scale, bs0);
            c[nt][1] = fmaf(c[nt][1], scale, bs1);
            c[nt][2] = fmaf(c[nt][2], scale, bs0);
            c[nt][3] = fmaf(c[nt][3], scale, bs1);
            rx0 = fmaxf(rx0, fmaxf(c[nt][0], c[nt][1]));
            rx1 = fmaxf(rx1, fmaxf(c[nt][2], c[nt][3]));
        }
        rx0 = fmaxf(rx0, __shfl_xor_sync(0xffffffffu, rx0, 1));
        rx0 = fmaxf(rx0, __shfl_xor_sync(0xffffffffu, rx0, 2));
        rx1 = fmaxf(rx1, __shfl_xor_sync(0xffffffffu, rx1, 1));
        rx1 = fmaxf(rx1, __shfl_xor_sync(0xffffffffu, rx1, 2));

        float mn0 = fmaxf(m0, rx0), mn1 = fmaxf(m1, rx1);
        float al0 = __expf(m0 - mn0), al1 = __expf(m1 - mn1);
        m0 = mn0; m1 = mn1;

        float ps0 = 0.f, ps1 = 0.f;
#pragma unroll
        for (int nt = 0; nt < 8; nt++) {
            c[nt][0] = __expf(c[nt][0] - m0);
            c[nt][1] = __expf(c[nt][1] - m0);
            c[nt][2] = __expf(c[nt][2] - m1);
            c[nt][3] = __expf(c[nt][3] - m1);
            ps0 += c[nt][0] + c[nt][1];
            ps1 += c[nt][2] + c[nt][3];
        }
        ps0 += __shfl_xor_sync(0xffffffffu, ps0, 1);
        ps0 += __shfl_xor_sync(0xffffffffu, ps0, 2);
        ps1 += __shfl_xor_sync(0xffffffffu, ps1, 1);
        ps1 += __shfl_xor_sync(0xffffffffu, ps1, 2);
        l0 = l0 * al0 + ps0;
        l1 = l1 * al1 + ps1;

#pragma unroll
        for (int n = 0; n < 16; n++) {
            o[n][0] *= al0; o[n][1] *= al0;
            o[n][2] *= al1; o[n][3] *= al1;
        }

        // ---- O += P V : P hi/lo from registers, pass-split, V frags cached ----
#pragma unroll
        for (int kc = 0; kc < 4; kc++) {
            float2 f0 = make_float2(c[2 * kc][0],     c[2 * kc][1]);
            float2 f1 = make_float2(c[2 * kc][2],     c[2 * kc][3]);
            float2 f2 = make_float2(c[2 * kc + 1][0], c[2 * kc + 1][1]);
            float2 f3 = make_float2(c[2 * kc + 1][2], c[2 * kc + 1][3]);
            __half2 ah0 = __float22half2_rn(f0);
            __half2 ah1 = __float22half2_rn(f1);
            __half2 ah2 = __float22half2_rn(f2);
            __half2 ah3 = __float22half2_rn(f3);
            float2 r0 = __half22float2(ah0), r1 = __half22float2(ah1);
            float2 r2 = __half22float2(ah2), r3 = __half22float2(ah3);
            __half2 al_0 = __float22half2_rn(make_float2(f0.x - r0.x, f0.y - r0.y));
            __half2 al_1 = __float22half2_rn(make_float2(f1.x - r1.x, f1.y - r1.y));
            __half2 al_2 = __float22half2_rn(make_float2(f2.x - r2.x, f2.y - r2.y));
            __half2 al_3 = __float22half2_rn(make_float2(f3.x - r3.x, f3.y - r3.y));
            uint32_t Ah0 = h2u(ah0), Ah1 = h2u(ah1), Ah2 = h2u(ah2), Ah3 = h2u(ah3);
            uint32_t Al0 = h2u(al_0), Al1 = h2u(al_1), Al2 = h2u(al_2), Al3 = h2u(al_3);
            const int off = kc * 32 + t * 8;
            uint2 bv[16];
#pragma unroll
            for (int nt = 0; nt < 16; nt++) {
                bv[nt] = *(const uint2*)(vb + nt * (8 * RV) + off);
                MMA16(o[nt], Ah0, Ah1, Ah2, Ah3, bv[nt].x, bv[nt].y);
            }
#pragma unroll
            for (int nt = 0; nt < 16; nt++)
                MMA16(o[nt], Al0, Al1, Al2, Al3, bv[nt].x, bv[nt].y);
        }

        __syncthreads();
        if (kt + 2 < NT) {
            ISSUE_TILE(kt + 2, s);
            cpa_commit();
        }
    }

    // ---- epilogue ----
    float i0 = 1.f / l0, i1 = 1.f / l1;
    long base = ((long)b * SL + q0 + qrow) * DIM;
#pragma unroll
    for (int nt = 0; nt < 16; nt++) {
        float2 r0, r1;
        r0.x = o[nt][0] * i0; r0.y = o[nt][1] * i0;
        r1.x = o[nt][2] * i1; r1.y = o[nt][3] * i1;
        *(float2*)&out[base + nt * 8 + 2 * t] = r0;
        *(float2*)&out[base + 8 * DIM + nt * 8 + 2 * t] = r1;
    }
}

// ---------------------------------------------------------------------------
extern "C" void kernel_launch(void* const* d_in, const int* in_sizes, int n_in,
                              void* d_out, int out_size) {
    (void)in_sizes; (void)n_in; (void)out_size;
    const float* query = (const float*)d_in[0];
    const float* key   = (const float*)d_in[1];
    const float* value = (const float*)d_in[2];
    const float* Wq    = (const float*)d_in[3];
    const float* Wk    = (const float*)d_in[4];
    const float* Wv    = (const float*)d_in[5];
    const int*   mask  = (const int*)d_in[6];
    float* out = (float*)d_out;

    const int projSmem = (128 * 128 + 64 * 132) * (int)sizeof(float);
    cudaFuncSetAttribute(proj_all, cudaFuncAttributeMaxDynamicSharedMemorySize, projSmem);
    cudaFuncSetAttribute(attn_kernel, cudaFuncAttributeMaxDynamicSharedMemorySize, SMEM_ATTN);

    proj_all<<<3 * 256, 256, projSmem>>>(query, key, value, Wq, Wk, Wv);
    attn_kernel<<<NB * SL / BQ, 256, SMEM_ATTN>>>(mask, out);
}

// round 10
// speedup vs baseline: 4.3743x; 1.1253x over previous
#include <cuda_runtime.h>
#include <cuda_fp16.h>
#include <cstdint>

#define NB  8
#define SL  2048
#define DIM 128
#define BQ  128
#define BK  64
#define NT  (SL / BK)     // 32 K-tiles

// smem byte strides
#define RQ  288           // Q/K row: 128 halves (256B) + 32B pad  -> banks 8g+2t
#define RV  160           // Vt row: 64 halves (128B) + 32B pad

// smem byte offsets (all 16B aligned). Total 152,064 B -> 1 CTA/SM.
#define OQH 0
#define OKH (OQH + BQ * RQ)            // 36864  (2 bufs x 64*288)
#define OKL (OKH + 2 * BK * RQ)        // 73728
#define OVT (OKL + 2 * BK * RQ)        // 110592 (2 bufs x 128*160)
#define OMK (OVT + 2 * DIM * RV)       // 151552 (2 x 256B)
#define SMEM_ATTN (OMK + 2 * 256)      // 152064

// Projected tensors: Q hi-only; K hi+lo fp16 split; V transposed half.
// Columns pair-permuted to match MMA fragment layout.
__device__ __half g_qhi[NB * SL * DIM];
__device__ __half g_khi[NB * SL * DIM];
__device__ __half g_klo[NB * SL * DIM];
__device__ __half g_vt [NB * DIM * SL];   // [b][dim][key], key pair-permuted

__device__ __forceinline__ uint32_t h2u(__half2 h) {
    return *reinterpret_cast<uint32_t*>(&h);
}
__device__ __forceinline__ void cpa16(uint32_t saddr, const void* gaddr) {
    asm volatile("cp.async.ca.shared.global [%0], [%1], 16;\n"
                 :: "r"(saddr), "l"(gaddr));
}
__device__ __forceinline__ void cpa_commit() {
    asm volatile("cp.async.commit_group;\n" ::: "memory");
}

#define MMA16(C, A0, A1, A2, A3, B0, B1)                                     \
    asm volatile(                                                            \
        "mma.sync.aligned.m16n8k16.row.col.f32.f16.f16.f32 "                 \
        "{%0,%1,%2,%3},{%4,%5,%6,%7},{%8,%9},{%0,%1,%2,%3};"                 \
        : "+f"(C[0]), "+f"(C[1]), "+f"(C[2]), "+f"(C[3])                     \
        : "r"(A0), "r"(A1), "r"(A2), "r"(A3), "r"(B0), "r"(B1))

// Pair permutation within a 16-col chunk: pair p (cols 2p,2p+1) -> word w.
__host__ __device__ __forceinline__ int permloc(int loc) {
    int p = loc >> 1, h = loc & 1;
    int w = (p < 4) ? (2 * p) : (2 * (p - 4) + 1);
    return 2 * w + h;
}

// ---------------------------------------------------------------------------
// Fused projections: sel = blockIdx.x>>8 picks {Q, K, V}.
//   Q: hi fp16, pair-permuted.   K: hi+lo fp16, pair-permuted.
//   V: half, transposed to g_vt[b][dim][key], keys pair-permuted.
// Q/K outputs staged in smem -> coalesced 16B STG.
// ---------------------------------------------------------------------------
__global__ __launch_bounds__(256, 2)
void proj_all(const float* __restrict__ Xq, const float* __restrict__ Xk,
              const float* __restrict__ Xv, const float* __restrict__ Wq,
              const float* __restrict__ Wk, const float* __restrict__ Wv) {
    extern __shared__ float sm[];
    float* sW = sm;               // 128*128
    float* sX = sm + 128 * 128;   // 64 rows, stride 132
    __half* sT = (__half*)sm;     // V path reuse: 64 x 136 halves

    const int sel = blockIdx.x >> 8;
    const int blk = blockIdx.x & 255;
    const float* X = (sel == 0) ? Xq : (sel == 1) ? Xk : Xv;
    const float* W = (sel == 0) ? Wq : (sel == 1) ? Wk : Wv;

    const int tid = threadIdx.x;
    const long r0 = (long)blk * 64;

    for (int idx = tid; idx < 128 * 32; idx += 256) {
        int row = idx >> 5, k4 = (idx & 31) << 2;
        *(float4*)&sW[row * 128 + k4] = *(const float4*)&W[row * 128 + k4];
    }
    for (int idx = tid; idx < 64 * 32; idx += 256) {
        int row = idx >> 5, k4 = (idx & 31) << 2;
        *(float4*)&sX[row * 132 + k4] = *(const float4*)&X[(r0 + row) * DIM + k4];
    }
    __syncthreads();

    const int tr = tid >> 4;
    const int tc = tid & 15;

    float acc[4][8];
#pragma unroll
    for (int i = 0; i < 4; i++)
#pragma unroll
        for (int j = 0; j < 8; j++) acc[i][j] = 0.f;

#pragma unroll 4
    for (int k = 0; k < 128; k++) {
        float xv[4], wv[8];
#pragma unroll
        for (int i = 0; i < 4; i++) xv[i] = sX[(tr * 4 + i) * 132 + k];
#pragma unroll
        for (int j = 0; j < 8; j++) wv[j] = sW[k * 128 + tc + 16 * j];
#pragma unroll
        for (int i = 0; i < 4; i++)
#pragma unroll
            for (int j = 0; j < 8; j++) acc[i][j] = fmaf(xv[i], wv[j], acc[i][j]);
    }

    if (sel < 2) {
        // Stage permuted fp16 outputs in smem, then coalesced 16B stores.
        __syncthreads();   // done reading sW/sX
        __half* sHi = (__half*)sm;            // 64*128 halves (16KB)
        __half* sLo = sHi + 64 * 128;         // 64*128 halves (16KB)
        const int locp = permloc(tc);
#pragma unroll
        for (int i = 0; i < 4; i++)
#pragma unroll
            for (int j = 0; j < 8; j++) {
                int sidx = (tr * 4 + i) * 128 + 16 * j + locp;
                float y  = acc[i][j];
                __half hi = __float2half_rn(y);
                sHi[sidx] = hi;
                if (sel == 1) sLo[sidx] = __float2half_rn(y - __half2float(hi));
            }
        __syncthreads();
        __half* Yh = (sel == 0) ? g_qhi : g_khi;
        for (int idx = tid; idx < 64 * 16; idx += 256) {
            int row = idx >> 4, c16 = idx & 15;
            *(uint4*)&Yh[(r0 + row) * DIM + c16 * 8] =
                *(const uint4*)&sHi[row * 128 + c16 * 8];
            if (sel == 1)
                *(uint4*)&g_klo[(r0 + row) * DIM + c16 * 8] =
                    *(const uint4*)&sLo[row * 128 + c16 * 8];
        }
    } else {
        const int bb = (int)(r0 >> 11);
        const int k0 = (int)(r0 & 2047);
        __syncthreads();   // done reading sW/sX; reuse as sT
#pragma unroll
        for (int i = 0; i < 4; i++)
#pragma unroll
            for (int j = 0; j < 8; j++)
                sT[(tr * 4 + i) * 136 + tc + 16 * j] = __float2half_rn(acc[i][j]);
        __syncthreads();

        const int w    = tid >> 5;
        const int lane = tid & 31;
        const int pc   = lane >> 3;
        const int pl   = lane & 7;
        const int wd   = (pl < 4) ? (2 * pl) : (2 * (pl - 4) + 1);
        const int dstk = k0 + pc * 16 + 2 * wd;
#pragma unroll
        for (int m = 0; m < 16; m++) {
            int d = w * 16 + m;
            __half2 h2 = __halves2half2(sT[(2 * lane) * 136 + d],
                                        (__half)sT[(2 * lane + 1) * 136 + d]);
            *(uint32_t*)&g_vt[((long)bb * DIM + d) * SL + dstk] = h2u(h2);
        }
    }
}

// ---------------------------------------------------------------------------
// Flash attention, fp16 mma.sync m16n8k16, cp.async double buffer.
// S = Qhi*(Khi+Klo); P single fp16 from registers; l-reduce deferred
// past PV MMA issue; exp/cvt interleaved with PV chunks.
// ---------------------------------------------------------------------------
__global__ __launch_bounds__(256, 1)
void attn_kernel(const int* __restrict__ mask, float* __restrict__ out) {
    extern __shared__ char smem[];
    const uint32_t sb = (uint32_t)__cvta_generic_to_shared(smem);

    const int tid  = threadIdx.x;
    const int w    = tid >> 5;
    const int lane = tid & 31;
    const int g    = lane >> 2;
    const int t    = lane & 3;
    const int b    = blockIdx.x >> 4;
    const int q0   = (blockIdx.x & 15) << 7;

    const __half* gqh = g_qhi + ((long)b * SL + q0) * DIM;
    const __half* gkh = g_khi + (long)b * SL * DIM;
    const __half* gkl = g_klo + (long)b * SL * DIM;
    const __half* gvt = g_vt  + (long)b * DIM * SL;
    const int*    gmk = mask  + (long)b * SL;

    // ---- issue Q(hi) + tile0 as group 0; tile1 as group 1 ----
    for (int i = tid; i < 2048; i += 256) {
        int r = i >> 4, c = i & 15;
        cpa16(sb + OQH + r * RQ + c * 16, gqh + r * DIM + c * 8);
    }
#define ISSUE_TILE(kt, s)                                                     \
    {                                                                         \
        const int n0_ = (kt) * BK;                                            \
        for (int i = tid; i < 3088; i += 256) {                               \
            if (i < 1024) {                                                   \
                int r = i >> 4, c = i & 15;                                   \
                cpa16(sb + OKH + (s) * (BK * RQ) + r * RQ + c * 16,           \
                      gkh + (long)(n0_ + r) * DIM + c * 8);                   \
            } else if (i < 2048) {                                            \
                int j = i - 1024, r = j >> 4, c = j & 15;                     \
                cpa16(sb + OKL + (s) * (BK * RQ) + r * RQ + c * 16,           \
                      gkl + (long)(n0_ + r) * DIM + c * 8);                   \
            } else if (i < 3072) {                                            \
                int j = i - 2048, r = j >> 3, c = j & 7;                      \
                cpa16(sb + OVT + (s) * (DIM * RV) + r * RV + c * 16,          \
                      gvt + (long)r * SL + n0_ + c * 8);                      \
            } else {                                                          \
                int j = i - 3072;                                             \
                cpa16(sb + OMK + (s) * 256 + j * 16, gmk + n0_ + j * 4);      \
            }                                                                 \
        }                                                                     \
    }
    ISSUE_TILE(0, 0);
    cpa_commit();
    ISSUE_TILE(1, 1);
    cpa_commit();

    const int qrow = (w << 4) + g;
    const char* qh0 = smem + OQH + qrow * RQ;
    const char* qh1 = qh0 + 8 * RQ;

    float o[16][4];
#pragma unroll
    for (int n = 0; n < 16; n++)
#pragma unroll
        for (int j = 0; j < 4; j++) o[n][j] = 0.f;
    float m0 = -1e30f, m1 = -1e30f, l0 = 0.f, l1 = 0.f;
    const float scale = 0.08838834764831845f;

    for (int kt = 0; kt < NT; kt++) {
        const int s = kt & 1;
        if (kt < NT - 1)
            asm volatile("cp.async.wait_group 1;\n" ::: "memory");
        else
            asm volatile("cp.async.wait_group 0;\n" ::: "memory");
        __syncthreads();

        const char* kh = smem + OKH + s * (BK * RQ) + g * RQ;
        const char* kl = smem + OKL + s * (BK * RQ) + g * RQ;
        const char* vb = smem + OVT + s * (DIM * RV) + g * RV;
        const int*  mk = (const int*)(smem + OMK + s * 256);

        // ---- S = Qhi*(Khi + Klo), pass-split over nt for ILP ----
        float c[8][4];
#pragma unroll
        for (int n = 0; n < 8; n++)
#pragma unroll
            for (int j = 0; j < 4; j++) c[n][j] = 0.f;

#pragma unroll
        for (int kc = 0; kc < 8; kc++) {
            const int off = kc * 32 + t * 8;
            uint2 h0 = *(const uint2*)(qh0 + off);   // {a0, a2}
            uint2 h1 = *(const uint2*)(qh1 + off);   // {a1, a3}
#pragma unroll
            for (int nt = 0; nt < 8; nt++) {
                uint2 bh = *(const uint2*)(kh + nt * (8 * RQ) + off);
                MMA16(c[nt], h0.x, h1.x, h0.y, h1.y, bh.x, bh.y);
            }
#pragma unroll
            for (int nt = 0; nt < 8; nt++) {
                uint2 bl = *(const uint2*)(kl + nt * (8 * RQ) + off);
                MMA16(c[nt], h0.x, h1.x, h0.y, h1.y, bl.x, bl.y);
            }
        }

        // ---- scale + mask bias + row max ----
        float rx0 = -1e30f, rx1 = -1e30f;
#pragma unroll
        for (int nt = 0; nt < 8; nt++) {
            float bs0 = mk[nt * 8 + 2 * t]     ? 0.f : -1e30f;
            float bs1 = mk[nt * 8 + 2 * t + 1] ? 0.f : -1e30f;
            c[nt][0] = fmaf(c[nt][0], scale, bs0);
            c[nt][1] = fmaf(c[nt][1], scale, bs1);
            c[nt][2] = fmaf(c[nt][2], scale, bs0);
            c[nt][3] = fmaf(c[nt][3], scale, bs1);
            rx0 = fmaxf(rx0, fmaxf(c[nt][0], c[nt][1]));
            rx1 = fmaxf(rx1, fmaxf(c[nt][2], c[nt][3]));
        }
        rx0 = fmaxf(rx0, __shfl_xor_sync(0xffffffffu, rx0, 1));
        rx0 = fmaxf(rx0, __shfl_xor_sync(0xffffffffu, rx0, 2));
        rx1 = fmaxf(rx1, __shfl_xor_sync(0xffffffffu, rx1, 1));
        rx1 = fmaxf(rx1, __shfl_xor_sync(0xffffffffu, rx1, 2));

        float mn0 = fmaxf(m0, rx0), mn1 = fmaxf(m1, rx1);
        float al0 = __expf(m0 - mn0), al1 = __expf(m1 - mn1);
        m0 = mn0; m1 = mn1;

        // rescale O before accumulating this tile
#pragma unroll
        for (int n = 0; n < 16; n++) {
            o[n][0] *= al0; o[n][1] *= al0;
            o[n][2] *= al1; o[n][3] *= al1;
        }

        // ---- exp -> fp16 P -> PV MMA, chunk-interleaved (single pass) ----
#pragma unroll
        for (int kc = 0; kc < 4; kc++) {
            float e0 = __expf(c[2 * kc][0] - m0);
            float e1 = __expf(c[2 * kc][1] - m0);
            float e2 = __expf(c[2 * kc][2] - m1);
            float e3 = __expf(c[2 * kc][3] - m1);
            float e4 = __expf(c[2 * kc + 1][0] - m0);
            float e5 = __expf(c[2 * kc + 1][1] - m0);
            float e6 = __expf(c[2 * kc + 1][2] - m1);
            float e7 = __expf(c[2 * kc + 1][3] - m1);
            c[2 * kc][0] = e0; c[2 * kc][1] = e1;
            c[2 * kc][2] = e2; c[2 * kc][3] = e3;
            c[2 * kc + 1][0] = e4; c[2 * kc + 1][1] = e5;
            c[2 * kc + 1][2] = e6; c[2 * kc + 1][3] = e7;
            uint32_t A0 = h2u(__floats2half2_rn(e0, e1));
            uint32_t A1 = h2u(__floats2half2_rn(e2, e3));
            uint32_t A2 = h2u(__floats2half2_rn(e4, e5));
            uint32_t A3 = h2u(__floats2half2_rn(e6, e7));
            const int off = kc * 32 + t * 8;
#pragma unroll
            for (int nt = 0; nt < 16; nt++) {
                uint2 bv = *(const uint2*)(vb + nt * (8 * RV) + off);
                MMA16(o[nt], A0, A1, A2, A3, bv.x, bv.y);
            }
        }

        // ---- deferred l update (overlaps PV MMA execution) ----
        float ps0 = 0.f, ps1 = 0.f;
#pragma unroll
        for (int nt = 0; nt < 8; nt++) {
            ps0 += c[nt][0] + c[nt][1];
            ps1 += c[nt][2] + c[nt][3];
        }
        ps0 += __shfl_xor_sync(0xffffffffu, ps0, 1);
        ps0 += __shfl_xor_sync(0xffffffffu, ps0, 2);
        ps1 += __shfl_xor_sync(0xffffffffu, ps1, 1);
        ps1 += __shfl_xor_sync(0xffffffffu, ps1, 2);
        l0 = l0 * al0 + ps0;
        l1 = l1 * al1 + ps1;

        __syncthreads();
        if (kt + 2 < NT) {
            ISSUE_TILE(kt + 2, s);
            cpa_commit();
        }
    }

    // ---- epilogue ----
    float i0 = 1.f / l0, i1 = 1.f / l1;
    long base = ((long)b * SL + q0 + qrow) * DIM;
#pragma unroll
    for (int nt = 0; nt < 16; nt++) {
        float2 r0, r1;
        r0.x = o[nt][0] * i0; r0.y = o[nt][1] * i0;
        r1.x = o[nt][2] * i1; r1.y = o[nt][3] * i1;
        *(float2*)&out[base + nt * 8 + 2 * t] = r0;
        *(float2*)&out[base + 8 * DIM + nt * 8 + 2 * t] = r1;
    }
}

// ---------------------------------------------------------------------------
extern "C" void kernel_launch(void* const* d_in, const int* in_sizes, int n_in,
                              void* d_out, int out_size) {
    (void)in_sizes; (void)n_in; (void)out_size;
    const float* query = (const float*)d_in[0];
    const float* key   = (const float*)d_in[1];
    const float* value = (const float*)d_in[2];
    const float* Wq    = (const float*)d_in[3];
    const float* Wk    = (const float*)d_in[4];
    const float* Wv    = (const float*)d_in[5];
    const int*   mask  = (const int*)d_in[6];
    float* out = (float*)d_out;

    const int projSmem = (128 * 128 + 64 * 132) * (int)sizeof(float);
    cudaFuncSetAttribute(proj_all, cudaFuncAttributeMaxDynamicSharedMemorySize, projSmem);
    cudaFuncSetAttribute(attn_kernel, cudaFuncAttributeMaxDynamicSharedMemorySize, SMEM_ATTN);

    proj_all<<<3 * 256, 256, projSmem>>>(query, key, value, Wq, Wk, Wv);
    attn_kernel<<<NB * SL / BQ, 256, SMEM_ATTN>>>(mask, out);
}